// round 11
// baseline (speedup 1.0000x reference)
#include <cuda_runtime.h>
#include <cuda_fp16.h>
#include <math.h>
#include <stdint.h>

#define B_    2
#define C_IN  256
#define N_TOK 2304
#define H_    8
#define DH    64
#define NKV   2305    // n + 1 null token
#define NKVP  2368    // padded (37*64)

typedef unsigned int u32;

// -------- scratch (device globals, zero-init) --------
__device__ float  g_invl2[B_ * N_TOK];
__device__ __half g_kb[B_ * H_ * NKV * DH];    // [bh][j][d]; row0=null k, row j=q[j-1]; f16
__device__ __half g_vT[B_ * H_ * DH * NKVP];   // [bh][d][j]; col0=null v; f16; pad zeros
__device__ float  g_k2[B_ * H_ * NKVP];        // |k|^2 of f16-rounded rows; pad zeros
__device__ float  g_po[2 * B_ * H_ * DH * N_TOK]; // split-KV partial O (unnormalized)
__device__ float  g_pl[2 * B_ * H_ * N_TOK];      // split-KV partial l
__device__ float  g_o [B_ * H_ * DH * N_TOK];  // combined attn out [bh][d][i] fp32

// -------- helpers --------
__device__ __forceinline__ void mmaf16(float c[4], const u32 a[4], u32 b0, u32 b1) {
    asm("mma.sync.aligned.m16n8k16.row.col.f32.f16.f16.f32 "
        "{%0,%1,%2,%3},{%4,%5,%6,%7},{%8,%9},{%0,%1,%2,%3};"
        : "+f"(c[0]), "+f"(c[1]), "+f"(c[2]), "+f"(c[3])
        : "r"(a[0]), "r"(a[1]), "r"(a[2]), "r"(a[3]), "r"(b0), "r"(b1));
}
__device__ __forceinline__ u32 packh2(float hi, float lo) {
    u32 r; asm("cvt.rn.f16x2.f32 %0, %1, %2;" : "=r"(r) : "f"(hi), "f"(lo)); return r;
}
__device__ __forceinline__ void cpasync16(u32 dst, const void* src) {
    asm volatile("cp.async.ca.shared.global [%0], [%1], 16;" :: "r"(dst), "l"(src));
}
__device__ __forceinline__ void cpcommit() { asm volatile("cp.async.commit_group;"); }

// ---------------- 0) null token rows ----------------
__global__ void null_init(const float* __restrict__ nullkv) {
    int tid = threadIdx.x;  // 128
#pragma unroll
    for (int t = 0; t < 8; t++) {
        int idx = tid + 128 * t;                 // 0..1023
        int bh = idx >> 6, d = idx & 63, h = bh & 7;
        g_kb[(size_t)bh * NKV * DH + d]  = __float2half_rn(nullkv[h * DH + d]);
        g_vT[((size_t)bh * DH + d) * NKVP] = __float2half_rn(nullkv[H_ * DH + h * DH + d]);
    }
    if (tid < 16) {
        int h = tid & 7; float s = 0.f;
#pragma unroll 8
        for (int d = 0; d < 64; d++) {
            float x = __half2float(__float2half_rn(nullkv[h * DH + d]));
            s = fmaf(x, x, s);
        }
        g_k2[(size_t)tid * NKVP] = s;
    }
}

// ---------------- 1) per-token inverse L2 norm ----------------
__global__ __launch_bounds__(256) void norm_kernel(const float* __restrict__ fmap) {
    __shared__ float part[8][33];
    int i_loc = threadIdx.x & 31, cg = threadIdx.x >> 5;
    int idx = blockIdx.x * 32 + i_loc;
    int bb = idx / N_TOK, i = idx - bb * N_TOK;
    const float* p = fmap + (size_t)bb * C_IN * N_TOK + (size_t)cg * 32 * N_TOK + i;
    float s = 0.f;
#pragma unroll 8
    for (int c = 0; c < 32; c++) { float x = p[(size_t)c * N_TOK]; s = fmaf(x, x, s); }
    part[cg][i_loc] = s;
    __syncthreads();
    if (threadIdx.x < 32) {
        float t = 0.f;
#pragma unroll
        for (int g = 0; g < 8; g++) t += part[g][threadIdx.x];
        g_invl2[blockIdx.x * 32 + threadIdx.x] = 16.0f / fmaxf(sqrtf(t), 1e-12f);
    }
}

// ---------------- 2) fused qk/v projection GEMM ----------------
__global__ __launch_bounds__(256) void proj_kernel(const float* __restrict__ fmap,
                                                   const float* __restrict__ gamma,
                                                   const float* __restrict__ w_qk,
                                                   const float* __restrict__ w_v) {
    __shared__ float As[16][64];
    __shared__ float Bs[16][64];
    const int i0 = blockIdx.x * 64;
    const int o0 = blockIdx.y * 64;
    const int bb = blockIdx.z;
    const bool isv = (o0 >= 512);
    const float* W = isv ? (w_v + (o0 - 512) * C_IN) : (w_qk + o0 * C_IN);
    const int h = (isv ? (o0 - 512) : o0) >> 6;
    const int bh = bb * H_ + h;

    const int tid = threadIdx.x;
    const int tr = tid >> 4, tc = tid & 15;
    const int ii = tid & 63, kq = tid >> 6;
    const int kkb = tid & 15, ob = tid >> 4;
    const float* Ab = fmap + (size_t)bb * C_IN * N_TOK + i0;

    float acc[4][4] = {};
    for (int k0 = 0; k0 < C_IN; k0 += 16) {
#pragma unroll
        for (int t = 0; t < 4; t++) {
            int kk = kq * 4 + t;
            As[kk][ii] = Ab[(size_t)(k0 + kk) * N_TOK + ii] * gamma[k0 + kk];
        }
#pragma unroll
        for (int t = 0; t < 4; t++) {
            int o = ob + 16 * t;
            Bs[kkb][o] = W[o * C_IN + k0 + kkb];
        }
        __syncthreads();
#pragma unroll
        for (int kk = 0; kk < 16; kk++) {
            float a[4], b[4];
#pragma unroll
            for (int x = 0; x < 4; x++) a[x] = As[kk][tr * 4 + x];
#pragma unroll
            for (int y = 0; y < 4; y++) b[y] = Bs[kk][tc * 4 + y];
#pragma unroll
            for (int x = 0; x < 4; x++)
#pragma unroll
                for (int y = 0; y < 4; y++) acc[x][y] = fmaf(a[x], b[y], acc[x][y]);
        }
        __syncthreads();
    }
#pragma unroll
    for (int x = 0; x < 4; x++) {
        int i = i0 + tr * 4 + x;
        float sc = g_invl2[bb * N_TOK + i];
        if (!isv) {
            float rs = 0.f;
#pragma unroll
            for (int y = 0; y < 4; y++) {
                int d = tc * 4 + y;
                __half hv = __float2half_rn(acc[x][y] * sc);
                g_kb[((size_t)bh * NKV + i + 1) * DH + d] = hv;
                float rv = __half2float(hv);
                rs = fmaf(rv, rv, rs);
            }
            rs += __shfl_xor_sync(0xffffffffu, rs, 1);
            rs += __shfl_xor_sync(0xffffffffu, rs, 2);
            rs += __shfl_xor_sync(0xffffffffu, rs, 4);
            rs += __shfl_xor_sync(0xffffffffu, rs, 8);
            if (tc == 0) g_k2[(size_t)bh * NKVP + i + 1] = rs;
        } else {
#pragma unroll
            for (int y = 0; y < 4; y++) {
                int d = tc * 4 + y;
                g_vT[((size_t)bh * DH + d) * NKVP + i + 1] = __float2half_rn(acc[x][y] * sc);
            }
        }
    }
}

// ---------------- 3) flash attention: f16 mma, m=0 softmax, split-KV x2 ----------------
#define SMK_W  0                  // K tiles: 2 x 64 rows x 32 words (f16x2), XOR-swizzled
#define SMV_W  4096               // V^T tiles: same shape
#define SMK2_W 8192               // k2: 2 x 64 floats
#define SMP_W  8320               // P: 8 warps x 16 rows x 36 words
#define SM_TOT ((SMP_W + 8 * 16 * 36) * 4)   // 51712 B

__global__ __launch_bounds__(256, 3) void attn_mma_kernel() {
    extern __shared__ float sm[];
    u32* smw = (u32*)sm;
    const int tid = threadIdx.x, lane = tid & 31, w = tid >> 5;   // 8 warps
    const int i0 = blockIdx.x * 128;
    const int h = blockIdx.y >> 1, half = blockIdx.y & 1;
    const int bb = blockIdx.z, bh = bb * H_ + h;
    const __half* kb_g = g_kb + (size_t)bh * NKV * DH;
    const __half* vT_g = g_vT + (size_t)bh * DH * NKVP;
    const float*  k2g  = g_k2 + (size_t)bh * NKVP;
    u32 smu = (u32)__cvta_generic_to_shared(sm);

    const int r0 = lane >> 2, cq = lane & 3;
    const int iw  = i0 + w * 16;
    const int ig0 = iw + r0, ig1 = ig0 + 8;

    // Q A-fragments: q[i] = k[i+1]; f16 pairs direct from gmem
    u32 aq[4][4];
    {
        const __half* q0 = kb_g + (size_t)(ig0 + 1) * DH;
        const __half* q1 = kb_g + (size_t)(ig1 + 1) * DH;
#pragma unroll
        for (int kk = 0; kk < 4; kk++) {
            int d = kk * 16 + 2 * cq;
            aq[kk][0] = *(const u32*)(q0 + d);
            aq[kk][1] = *(const u32*)(q1 + d);
            aq[kk][2] = *(const u32*)(q0 + d + 8);
            aq[kk][3] = *(const u32*)(q1 + d + 8);
        }
    }
    const float q2r0 = k2g[ig0 + 1], q2r1 = k2g[ig1 + 1];

    float l0 = 0.f, l1 = 0.f;
    float o[8][4];
#pragma unroll
    for (int n = 0; n < 8; n++) { o[n][0] = o[n][1] = o[n][2] = o[n][3] = 0.f; }

    // tile loader: K 512 chunks + V 512 + k2 16 (16B each)
    auto load_tile = [&](int buf, int j0) {
#pragma unroll
        for (int it = 0; it < 5; it++) {
            int c = tid + 256 * it;                    // 0..1279, used < 1040
            if (c < 512) {
                int row = c >> 3, ch = c & 7, sw = ch ^ (row & 7);
                int jg = j0 + row; if (jg > NKV - 1) jg = NKV - 1;
                cpasync16(smu + (u32)(SMK_W + buf * 2048 + row * 32 + sw * 4) * 4,
                          kb_g + (size_t)jg * DH + ch * 8);
            } else if (c < 1024) {
                int cc = c - 512;
                int row = cc >> 3, ch = cc & 7, sw = ch ^ (row & 7);
                cpasync16(smu + (u32)(SMV_W + buf * 2048 + row * 32 + sw * 4) * 4,
                          vT_g + (size_t)row * NKVP + j0 + ch * 8);
            } else if (c < 1040) {
                int cc = c - 1024;
                cpasync16(smu + (u32)(SMK2_W + buf * 64 + cc * 4) * 4, k2g + j0 + cc * 4);
            }
        }
    };

    const int t_begin = half ? 19 : 0;
    const int t_end   = half ? 37 : 19;
    load_tile(0, t_begin * 64);
    cpcommit();

    for (int t = t_begin; t < t_end; t++) {
        const int j0 = t * 64, buf = (t - t_begin) & 1;
        if (t + 1 < t_end) {
            if (t > t_begin) __syncthreads();
            load_tile(buf ^ 1, (t + 1) * 64);
            cpcommit();
            asm volatile("cp.async.wait_group 1;");
        } else {
            asm volatile("cp.async.wait_group 0;");
        }
        __syncthreads();

        const u32* ksb = smw + SMK_W + buf * 2048;
        const u32* vsb = smw + SMV_W + buf * 2048;
        const float* k2s = sm + SMK2_W + buf * 64;
        u32* pw = smw + SMP_W + w * 16 * 36;

        // ---- S = Q K^T (32 mma) ----
        float sC[8][4];
#pragma unroll
        for (int n = 0; n < 8; n++) {
            sC[n][0] = sC[n][1] = sC[n][2] = sC[n][3] = 0.f;
            int rb = (n * 8 + r0) * 32;
#pragma unroll
            for (int kk = 0; kk < 4; kk++) {
                u32 b0 = ksb[rb + (((2 * kk)     ^ r0) * 4) + cq];
                u32 b1 = ksb[rb + (((2 * kk + 1) ^ r0) * 4) + cq];
                mmaf16(sC[n], aq[kk], b0, b1);
            }
        }

        // ---- p = exp(-sqrt(d2)/8) (m=0), masks, l accumulate ----
#pragma unroll
        for (int n = 0; n < 8; n++) {
            int jbase = j0 + n * 8;
            float2 kk2 = *(const float2*)(k2s + n * 8 + 2 * cq);
            float p0 = __expf(-0.125f * sqrtf(fmaxf(fmaf(-2.f, sC[n][0], q2r0 + kk2.x), 0.f)));
            float p1 = __expf(-0.125f * sqrtf(fmaxf(fmaf(-2.f, sC[n][1], q2r0 + kk2.y), 0.f)));
            float p2 = __expf(-0.125f * sqrtf(fmaxf(fmaf(-2.f, sC[n][2], q2r1 + kk2.x), 0.f)));
            float p3 = __expf(-0.125f * sqrtf(fmaxf(fmaf(-2.f, sC[n][3], q2r1 + kk2.y), 0.f)));
            if ((jbase <= iw + 16 && jbase + 8 > iw + 1) || (jbase + 8 > NKV)) {
                int jb = jbase + 2 * cq;
                if (jb == ig0 + 1 || jb >= NKV)         p0 = 0.f;
                if (jb + 1 == ig0 + 1 || jb + 1 >= NKV) p1 = 0.f;
                if (jb == ig1 + 1 || jb >= NKV)         p2 = 0.f;
                if (jb + 1 == ig1 + 1 || jb + 1 >= NKV) p3 = 0.f;
            }
            l0 += p0 + p1; l1 += p2 + p3;
            sC[n][0] = p0; sC[n][1] = p1; sC[n][2] = p2; sC[n][3] = p3;
        }

        // ---- stage P as f16x2 (per-warp region) ----
#pragma unroll
        for (int n = 0; n < 8; n++) {
            pw[r0 * 36 + n * 4 + cq]       = packh2(sC[n][1], sC[n][0]);
            pw[(r0 + 8) * 36 + n * 4 + cq] = packh2(sC[n][3], sC[n][2]);
        }
        __syncwarp();

        // ---- O += P V (32 mma) ----
#pragma unroll
        for (int kk = 0; kk < 4; kk++) {
            u32 ap[4];
            ap[0] = pw[r0 * 36 + kk * 8 + cq];
            ap[1] = pw[(r0 + 8) * 36 + kk * 8 + cq];
            ap[2] = pw[r0 * 36 + kk * 8 + cq + 4];
            ap[3] = pw[(r0 + 8) * 36 + kk * 8 + cq + 4];
#pragma unroll
            for (int n = 0; n < 8; n++) {
                int rb = (n * 8 + r0) * 32;
                u32 b0 = vsb[rb + (((2 * kk)     ^ r0) * 4) + cq];
                u32 b1 = vsb[rb + (((2 * kk + 1) ^ r0) * 4) + cq];
                mmaf16(o[n], ap, b0, b1);
            }
        }
    }

    // ---- epilogue: write unnormalized partials ----
    l0 += __shfl_xor_sync(~0u, l0, 1); l0 += __shfl_xor_sync(~0u, l0, 2);
    l1 += __shfl_xor_sync(~0u, l1, 1); l1 += __shfl_xor_sync(~0u, l1, 2);
    float* ob = g_po + (size_t)(half * 16 + bh) * DH * N_TOK;
#pragma unroll
    for (int n = 0; n < 8; n++) {
        int d = n * 8 + 2 * cq;
        ob[(size_t)d * N_TOK + ig0]       = o[n][0];
        ob[(size_t)(d + 1) * N_TOK + ig0] = o[n][1];
        ob[(size_t)d * N_TOK + ig1]       = o[n][2];
        ob[(size_t)(d + 1) * N_TOK + ig1] = o[n][3];
    }
    if (cq == 0) {
        g_pl[(size_t)(half * 16 + bh) * N_TOK + ig0] = l0;
        g_pl[(size_t)(half * 16 + bh) * N_TOK + ig1] = l1;
    }
}

// ---------------- 3b) combine split-KV halves ----------------
__global__ __launch_bounds__(256) void combine_kernel() {
    const int c = blockIdx.x * 256 + threadIdx.x;      // float4 index
    const int base = c * 4;
    const int i  = base % N_TOK;
    const int bh = (base / N_TOK) >> 6;
    const float4 a = *(const float4*)(g_po + base);
    const float4 b = *(const float4*)(g_po + (size_t)16 * DH * N_TOK + base);
    const float4 la = *(const float4*)(g_pl + (size_t)bh * N_TOK + i);
    const float4 lb = *(const float4*)(g_pl + (size_t)(16 + bh) * N_TOK + i);
    float4 r;
    r.x = __fdividef(a.x + b.x, la.x + lb.x);
    r.y = __fdividef(a.y + b.y, la.y + lb.y);
    r.z = __fdividef(a.z + b.z, la.z + lb.z);
    r.w = __fdividef(a.w + b.w, la.w + lb.w);
    *(float4*)(g_o + base) = r;
}

// ---------------- 4) output projection GEMM ----------------
__global__ __launch_bounds__(128) void outproj_kernel(const float* __restrict__ w_out,
                                                      float* __restrict__ out) {
    __shared__ float As[16][32];
    __shared__ float Bs[16][64];
    const int n0 = blockIdx.x * 64, o0 = blockIdx.y * 32, bb = blockIdx.z;
    const int tid = threadIdx.x, tr = tid >> 4, tc = tid & 15;
    const int kkA = tid & 15, oA = tid >> 4;
    const int nB = tid & 63, kB = tid >> 6;
    float acc[4][4] = {};
    for (int k0 = 0; k0 < 512; k0 += 16) {
#pragma unroll
        for (int t = 0; t < 4; t++) {
            int o = oA + 8 * t;
            As[kkA][o] = w_out[(o0 + o) * 512 + k0 + kkA];
        }
#pragma unroll
        for (int t = 0; t < 8; t++) {
            int kk = kB + 2 * t;
            Bs[kk][nB] = g_o[((size_t)bb * 512 + k0 + kk) * N_TOK + n0 + nB];
        }
        __syncthreads();
#pragma unroll
        for (int kk = 0; kk < 16; kk++) {
            float a[4], b[4];
#pragma unroll
            for (int x = 0; x < 4; x++) a[x] = As[kk][tr * 4 + x];
#pragma unroll
            for (int y = 0; y < 4; y++) b[y] = Bs[kk][tc * 4 + y];
#pragma unroll
            for (int x = 0; x < 4; x++)
#pragma unroll
                for (int y = 0; y < 4; y++) acc[x][y] = fmaf(a[x], b[y], acc[x][y]);
        }
        __syncthreads();
    }
#pragma unroll
    for (int x = 0; x < 4; x++)
#pragma unroll
        for (int y = 0; y < 4; y++)
            out[(size_t)bb * 256 * N_TOK + (size_t)(o0 + tr * 4 + x) * N_TOK + n0 + tc * 4 + y] = acc[x][y];
}

// ---------------- launch ----------------
extern "C" void kernel_launch(void* const* d_in, const int* in_sizes, int n_in,
                              void* d_out, int out_size) {
    const float* fmap   = (const float*)d_in[0];
    const float* gamma  = (const float*)d_in[1];
    const float* w_qk   = (const float*)d_in[2];
    const float* w_v    = (const float*)d_in[3];
    const float* nullkv = (const float*)d_in[4];
    const float* w_out  = (const float*)d_in[5];
    float* out = (float*)d_out;

    cudaFuncSetAttribute(attn_mma_kernel, cudaFuncAttributeMaxDynamicSharedMemorySize, SM_TOT);

    null_init<<<1, 128>>>(nullkv);
    norm_kernel<<<(B_ * N_TOK) / 32, 256>>>(fmap);
    proj_kernel<<<dim3(N_TOK / 64, 16, B_), 256>>>(fmap, gamma, w_qk, w_v);
    attn_mma_kernel<<<dim3(N_TOK / 128, H_ * 2, B_), 256, SM_TOT>>>();
    combine_kernel<<<(B_ * H_ * DH * N_TOK / 4) / 256, 256>>>();
    outproj_kernel<<<dim3(N_TOK / 64, 8, B_), 128>>>(w_out, out);
}

// round 12
// speedup vs baseline: 1.3033x; 1.3033x over previous
#include <cuda_runtime.h>
#include <cuda_fp16.h>
#include <math.h>
#include <stdint.h>

#define B_    2
#define C_IN  256
#define N_TOK 2304
#define H_    8
#define DH    64
#define NKV   2305    // n + 1 null token
#define NKVP  2368    // padded (37*64)

typedef unsigned int u32;

// -------- scratch (device globals, zero-init) --------
__device__ float  g_invl2[B_ * N_TOK];
__device__ float  g_wq[512 * C_IN];            // w_qk * gamma
__device__ float  g_wv[512 * C_IN];            // w_v  * gamma
__device__ __half g_kb[B_ * H_ * NKV * DH];    // [bh][j][d]; row0=null k, row j=q[j-1]; f16
__device__ __half g_vT[B_ * H_ * DH * NKVP];   // [bh][d][j]; col0=null v; f16; pad zeros
__device__ float  g_k2[B_ * H_ * NKVP];        // |k|^2 of f16-rounded rows; pad zeros
__device__ float  g_o [B_ * H_ * DH * N_TOK];  // attn out [bh][d][i] fp32

// -------- helpers --------
__device__ __forceinline__ void mmaf16(float c[4], const u32 a[4], u32 b0, u32 b1) {
    asm("mma.sync.aligned.m16n8k16.row.col.f32.f16.f16.f32 "
        "{%0,%1,%2,%3},{%4,%5,%6,%7},{%8,%9},{%0,%1,%2,%3};"
        : "+f"(c[0]), "+f"(c[1]), "+f"(c[2]), "+f"(c[3])
        : "r"(a[0]), "r"(a[1]), "r"(a[2]), "r"(a[3]), "r"(b0), "r"(b1));
}
__device__ __forceinline__ void mmat32(float c[4], const u32 a[4], u32 b0, u32 b1) {
    asm("mma.sync.aligned.m16n8k8.row.col.f32.tf32.tf32.f32 "
        "{%0,%1,%2,%3},{%4,%5,%6,%7},{%8,%9},{%0,%1,%2,%3};"
        : "+f"(c[0]), "+f"(c[1]), "+f"(c[2]), "+f"(c[3])
        : "r"(a[0]), "r"(a[1]), "r"(a[2]), "r"(a[3]), "r"(b0), "r"(b1));
}
__device__ __forceinline__ u32 packh2(float hi, float lo) {
    u32 r; asm("cvt.rn.f16x2.f32 %0, %1, %2;" : "=r"(r) : "f"(hi), "f"(lo)); return r;
}
__device__ __forceinline__ void cpasync16(u32 dst, const void* src) {
    asm volatile("cp.async.ca.shared.global [%0], [%1], 16;" :: "r"(dst), "l"(src));
}
__device__ __forceinline__ void cpcommit() { asm volatile("cp.async.commit_group;"); }

// ---------------- 0a) null token rows ----------------
__global__ void null_init(const float* __restrict__ nullkv) {
    int tid = threadIdx.x;  // 128
#pragma unroll
    for (int t = 0; t < 8; t++) {
        int idx = tid + 128 * t;                 // 0..1023
        int bh = idx >> 6, d = idx & 63, h = bh & 7;
        g_kb[(size_t)bh * NKV * DH + d]  = __float2half_rn(nullkv[h * DH + d]);
        g_vT[((size_t)bh * DH + d) * NKVP] = __float2half_rn(nullkv[H_ * DH + h * DH + d]);
    }
    if (tid < 16) {
        int h = tid & 7; float s = 0.f;
#pragma unroll 8
        for (int d = 0; d < 64; d++) {
            float x = __half2float(__float2half_rn(nullkv[h * DH + d]));
            s = fmaf(x, x, s);
        }
        g_k2[(size_t)tid * NKVP] = s;
    }
}

// ---------------- 0b) pre-scale weights by gamma ----------------
__global__ __launch_bounds__(256) void wscale_kernel(const float* __restrict__ w_qk,
                                                     const float* __restrict__ w_v,
                                                     const float* __restrict__ gamma) {
    int idx = blockIdx.x * 256 + threadIdx.x;    // 0 .. 512*256-1
    int c = idx & (C_IN - 1);
    float g = gamma[c];
    g_wq[idx] = w_qk[idx] * g;
    g_wv[idx] = w_v[idx] * g;
}

// ---------------- 1) per-token inverse L2 norm ----------------
__global__ __launch_bounds__(256) void norm_kernel(const float* __restrict__ fmap) {
    __shared__ float part[8][33];
    int i_loc = threadIdx.x & 31, cg = threadIdx.x >> 5;
    int idx = blockIdx.x * 32 + i_loc;
    int bb = idx / N_TOK, i = idx - bb * N_TOK;
    const float* p = fmap + (size_t)bb * C_IN * N_TOK + (size_t)cg * 32 * N_TOK + i;
    float s = 0.f;
#pragma unroll 8
    for (int c = 0; c < 32; c++) { float x = p[(size_t)c * N_TOK]; s = fmaf(x, x, s); }
    part[cg][i_loc] = s;
    __syncthreads();
    if (threadIdx.x < 32) {
        float t = 0.f;
#pragma unroll
        for (int g = 0; g < 8; g++) t += part[g][threadIdx.x];
        g_invl2[blockIdx.x * 32 + threadIdx.x] = 16.0f / fmaxf(sqrtf(t), 1e-12f);
    }
}

// ---------------- 2) qk/v projection via tf32 mma ----------------
// grid (18, 16, B): 128 i-rows x 64 o-cols (one head) per block, K=256
// smem words: As 2 x [16][136] (bank=8c+i), Bs 2 x [64][20] (bank=20o+c)
#define PA_ST 136
#define PB_ST 20
#define P_BUFA (16 * PA_ST)          // 2176 words per buffer
#define P_BSB  (2 * P_BUFA)          // 4352: Bs base
#define P_BUFB (64 * PB_ST)          // 1280 words per buffer

__global__ __launch_bounds__(256) void proj_mma_kernel(const float* __restrict__ fmap) {
    __shared__ float sm[P_BSB + 2 * P_BUFB];    // 27648 B
    u32* smw = (u32*)sm;
    u32 smu = (u32)__cvta_generic_to_shared(sm);

    const int tid = threadIdx.x, lane = tid & 31, w = tid >> 5;
    const int i0 = blockIdx.x * 128;
    const int y  = blockIdx.y;
    const bool isv = (y >= 8);
    const int h = y & 7;
    const int bb = blockIdx.z, bh = bb * H_ + h;
    const float* Wg = (isv ? g_wv : g_wq) + (size_t)h * 64 * C_IN;
    const float* Ab = fmap + (size_t)bb * C_IN * N_TOK + i0;

    const int r0 = lane >> 2, cq = lane & 3;
    const int il0 = w * 16 + r0;                 // local row
    const int ig0 = i0 + il0, ig1 = ig0 + 8;     // global rows

    float co[8][4];
#pragma unroll
    for (int n = 0; n < 8; n++) { co[n][0] = co[n][1] = co[n][2] = co[n][3] = 0.f; }

    // loader: A 512 chunks (16 c-rows x 32), B 256 chunks (64 o-rows x 4)
    auto load_tile = [&](int buf, int k0) {
#pragma unroll
        for (int it = 0; it < 3; it++) {
            int c = tid + 256 * it;              // 0..767
            if (c < 512) {
                int cr = c >> 5, ck = c & 31;
                cpasync16(smu + (u32)(buf * P_BUFA + cr * PA_ST + ck * 4) * 4,
                          Ab + (size_t)(k0 + cr) * N_TOK + ck * 4);
            } else {
                int cc = c - 512;
                int o = cc >> 2, ck = cc & 3;
                cpasync16(smu + (u32)(P_BSB + buf * P_BUFB + o * PB_ST + ck * 4) * 4,
                          Wg + (size_t)o * C_IN + k0 + ck * 4);
            }
        }
    };

    load_tile(0, 0);
    cpcommit();

    const int NKT = C_IN / 16;                   // 16 k-tiles
    for (int t = 0; t < NKT; t++) {
        const int buf = t & 1;
        if (t + 1 < NKT) {
            if (t >= 1) __syncthreads();
            load_tile(buf ^ 1, (t + 1) * 16);
            cpcommit();
            asm volatile("cp.async.wait_group 1;");
        } else {
            asm volatile("cp.async.wait_group 0;");
        }
        __syncthreads();

        const u32* As = smw + buf * P_BUFA;
        const u32* Bs = smw + P_BSB + buf * P_BUFB;
#pragma unroll
        for (int ks = 0; ks < 2; ks++) {
            int cb = ks * 8;
            u32 a[4];
            a[0] = As[(cb + cq) * PA_ST + il0];
            a[1] = As[(cb + cq) * PA_ST + il0 + 8];
            a[2] = As[(cb + cq + 4) * PA_ST + il0];
            a[3] = As[(cb + cq + 4) * PA_ST + il0 + 8];
#pragma unroll
            for (int n = 0; n < 8; n++) {
                u32 b0 = Bs[(n * 8 + r0) * PB_ST + cb + cq];
                u32 b1 = Bs[(n * 8 + r0) * PB_ST + cb + cq + 4];
                mmat32(co[n], a, b0, b1);
            }
        }
    }

    // ---- epilogue: *invl2 (fp32), round f16, write ----
    const float sc0 = g_invl2[bb * N_TOK + ig0];
    const float sc1 = g_invl2[bb * N_TOK + ig1];
    if (!isv) {
        float rs0 = 0.f, rs1 = 0.f;
#pragma unroll
        for (int n = 0; n < 8; n++) {
            int d = n * 8 + 2 * cq;
            u32 h0 = packh2(co[n][1] * sc0, co[n][0] * sc0);
            u32 h1 = packh2(co[n][3] * sc1, co[n][2] * sc1);
            *(u32*)&g_kb[((size_t)bh * NKV + ig0 + 1) * DH + d] = h0;
            *(u32*)&g_kb[((size_t)bh * NKV + ig1 + 1) * DH + d] = h1;
            __half2 hh0 = *(__half2*)&h0, hh1 = *(__half2*)&h1;
            float a0 = __low2float(hh0), a1 = __high2float(hh0);
            float b0f = __low2float(hh1), b1f = __high2float(hh1);
            rs0 = fmaf(a0, a0, fmaf(a1, a1, rs0));
            rs1 = fmaf(b0f, b0f, fmaf(b1f, b1f, rs1));
        }
        rs0 += __shfl_xor_sync(~0u, rs0, 1); rs0 += __shfl_xor_sync(~0u, rs0, 2);
        rs1 += __shfl_xor_sync(~0u, rs1, 1); rs1 += __shfl_xor_sync(~0u, rs1, 2);
        if (cq == 0) {
            g_k2[(size_t)bh * NKVP + ig0 + 1] = rs0;
            g_k2[(size_t)bh * NKVP + ig1 + 1] = rs1;
        }
    } else {
        __half* vb = g_vT + (size_t)bh * DH * NKVP;
#pragma unroll
        for (int n = 0; n < 8; n++) {
            int d = n * 8 + 2 * cq;
            vb[(size_t)d * NKVP + ig0 + 1]       = __float2half_rn(co[n][0] * sc0);
            vb[(size_t)(d + 1) * NKVP + ig0 + 1] = __float2half_rn(co[n][1] * sc0);
            vb[(size_t)d * NKVP + ig1 + 1]       = __float2half_rn(co[n][2] * sc1);
            vb[(size_t)(d + 1) * NKVP + ig1 + 1] = __float2half_rn(co[n][3] * sc1);
        }
    }
}

// ---------------- 3) flash attention: f16 mma, m=0 softmax (R10 winner) ----------------
#define SMK_W  0
#define SMV_W  4096
#define SMK2_W 8192
#define SMP_W  8320
#define SM_TOT ((SMP_W + 8 * 16 * 36) * 4)   // 51712 B

__global__ __launch_bounds__(256, 3) void attn_mma_kernel() {
    extern __shared__ float sm[];
    u32* smw = (u32*)sm;
    const int tid = threadIdx.x, lane = tid & 31, w = tid >> 5;   // 8 warps
    const int i0 = blockIdx.x * 128, h = blockIdx.y, bb = blockIdx.z;
    const int bh = bb * H_ + h;
    const __half* kb_g = g_kb + (size_t)bh * NKV * DH;
    const __half* vT_g = g_vT + (size_t)bh * DH * NKVP;
    const float*  k2g  = g_k2 + (size_t)bh * NKVP;
    u32 smu = (u32)__cvta_generic_to_shared(sm);

    const int r0 = lane >> 2, cq = lane & 3;
    const int iw  = i0 + w * 16;
    const int ig0 = iw + r0, ig1 = ig0 + 8;

    u32 aq[4][4];
    {
        const __half* q0 = kb_g + (size_t)(ig0 + 1) * DH;
        const __half* q1 = kb_g + (size_t)(ig1 + 1) * DH;
#pragma unroll
        for (int kk = 0; kk < 4; kk++) {
            int d = kk * 16 + 2 * cq;
            aq[kk][0] = *(const u32*)(q0 + d);
            aq[kk][1] = *(const u32*)(q1 + d);
            aq[kk][2] = *(const u32*)(q0 + d + 8);
            aq[kk][3] = *(const u32*)(q1 + d + 8);
        }
    }
    const float q2r0 = k2g[ig0 + 1], q2r1 = k2g[ig1 + 1];

    float l0 = 0.f, l1 = 0.f;
    float o[8][4];
#pragma unroll
    for (int n = 0; n < 8; n++) { o[n][0] = o[n][1] = o[n][2] = o[n][3] = 0.f; }

    auto load_tile = [&](int buf, int j0) {
#pragma unroll
        for (int it = 0; it < 5; it++) {
            int c = tid + 256 * it;
            if (c < 512) {
                int row = c >> 3, ch = c & 7, sw = ch ^ (row & 7);
                int jg = j0 + row; if (jg > NKV - 1) jg = NKV - 1;
                cpasync16(smu + (u32)(SMK_W + buf * 2048 + row * 32 + sw * 4) * 4,
                          kb_g + (size_t)jg * DH + ch * 8);
            } else if (c < 1024) {
                int cc = c - 512;
                int row = cc >> 3, ch = cc & 7, sw = ch ^ (row & 7);
                cpasync16(smu + (u32)(SMV_W + buf * 2048 + row * 32 + sw * 4) * 4,
                          vT_g + (size_t)row * NKVP + j0 + ch * 8);
            } else if (c < 1040) {
                int cc = c - 1024;
                cpasync16(smu + (u32)(SMK2_W + buf * 64 + cc * 4) * 4, k2g + j0 + cc * 4);
            }
        }
    };

    load_tile(0, 0);
    cpcommit();

    const int NT = (NKV + 63) / 64;   // 37
    for (int t = 0; t < NT; t++) {
        const int j0 = t * 64, buf = t & 1;
        if (t + 1 < NT) {
            if (t >= 1) __syncthreads();
            load_tile(buf ^ 1, j0 + 64);
            cpcommit();
            asm volatile("cp.async.wait_group 1;");
        } else {
            asm volatile("cp.async.wait_group 0;");
        }
        __syncthreads();

        const u32* ksb = smw + SMK_W + buf * 2048;
        const u32* vsb = smw + SMV_W + buf * 2048;
        const float* k2s = sm + SMK2_W + buf * 64;
        u32* pw = smw + SMP_W + w * 16 * 36;

        float sC[8][4];
#pragma unroll
        for (int n = 0; n < 8; n++) {
            sC[n][0] = sC[n][1] = sC[n][2] = sC[n][3] = 0.f;
            int rb = (n * 8 + r0) * 32;
#pragma unroll
            for (int kk = 0; kk < 4; kk++) {
                u32 b0 = ksb[rb + (((2 * kk)     ^ r0) * 4) + cq];
                u32 b1 = ksb[rb + (((2 * kk + 1) ^ r0) * 4) + cq];
                mmaf16(sC[n], aq[kk], b0, b1);
            }
        }

#pragma unroll
        for (int n = 0; n < 8; n++) {
            int jbase = j0 + n * 8;
            float2 kk2 = *(const float2*)(k2s + n * 8 + 2 * cq);
            float p0 = __expf(-0.125f * sqrtf(fmaxf(fmaf(-2.f, sC[n][0], q2r0 + kk2.x), 0.f)));
            float p1 = __expf(-0.125f * sqrtf(fmaxf(fmaf(-2.f, sC[n][1], q2r0 + kk2.y), 0.f)));
            float p2 = __expf(-0.125f * sqrtf(fmaxf(fmaf(-2.f, sC[n][2], q2r1 + kk2.x), 0.f)));
            float p3 = __expf(-0.125f * sqrtf(fmaxf(fmaf(-2.f, sC[n][3], q2r1 + kk2.y), 0.f)));
            if ((jbase <= iw + 16 && jbase + 8 > iw + 1) || (jbase + 8 > NKV)) {
                int jb = jbase + 2 * cq;
                if (jb == ig0 + 1 || jb >= NKV)         p0 = 0.f;
                if (jb + 1 == ig0 + 1 || jb + 1 >= NKV) p1 = 0.f;
                if (jb == ig1 + 1 || jb >= NKV)         p2 = 0.f;
                if (jb + 1 == ig1 + 1 || jb + 1 >= NKV) p3 = 0.f;
            }
            l0 += p0 + p1; l1 += p2 + p3;
            sC[n][0] = p0; sC[n][1] = p1; sC[n][2] = p2; sC[n][3] = p3;
        }

#pragma unroll
        for (int n = 0; n < 8; n++) {
            pw[r0 * 36 + n * 4 + cq]       = packh2(sC[n][1], sC[n][0]);
            pw[(r0 + 8) * 36 + n * 4 + cq] = packh2(sC[n][3], sC[n][2]);
        }
        __syncwarp();

#pragma unroll
        for (int kk = 0; kk < 4; kk++) {
            u32 ap[4];
            ap[0] = pw[r0 * 36 + kk * 8 + cq];
            ap[1] = pw[(r0 + 8) * 36 + kk * 8 + cq];
            ap[2] = pw[r0 * 36 + kk * 8 + cq + 4];
            ap[3] = pw[(r0 + 8) * 36 + kk * 8 + cq + 4];
#pragma unroll
            for (int n = 0; n < 8; n++) {
                int rb = (n * 8 + r0) * 32;
                u32 b0 = vsb[rb + (((2 * kk)     ^ r0) * 4) + cq];
                u32 b1 = vsb[rb + (((2 * kk + 1) ^ r0) * 4) + cq];
                mmaf16(o[n], ap, b0, b1);
            }
        }
    }

    l0 += __shfl_xor_sync(~0u, l0, 1); l0 += __shfl_xor_sync(~0u, l0, 2);
    l1 += __shfl_xor_sync(~0u, l1, 1); l1 += __shfl_xor_sync(~0u, l1, 2);
    float inv0 = 1.f / l0, inv1 = 1.f / l1;
    float* ob = g_o + (size_t)bh * DH * N_TOK;
#pragma unroll
    for (int n = 0; n < 8; n++) {
        int d = n * 8 + 2 * cq;
        ob[(size_t)d * N_TOK + ig0]       = o[n][0] * inv0;
        ob[(size_t)(d + 1) * N_TOK + ig0] = o[n][1] * inv0;
        ob[(size_t)d * N_TOK + ig1]       = o[n][2] * inv1;
        ob[(size_t)(d + 1) * N_TOK + ig1] = o[n][3] * inv1;
    }
}

// ---------------- 4) output projection GEMM ----------------
__global__ __launch_bounds__(128) void outproj_kernel(const float* __restrict__ w_out,
                                                      float* __restrict__ out) {
    __shared__ float As[16][32];
    __shared__ float Bs[16][64];
    const int n0 = blockIdx.x * 64, o0 = blockIdx.y * 32, bb = blockIdx.z;
    const int tid = threadIdx.x, tr = tid >> 4, tc = tid & 15;
    const int kkA = tid & 15, oA = tid >> 4;
    const int nB = tid & 63, kB = tid >> 6;
    float acc[4][4] = {};
    for (int k0 = 0; k0 < 512; k0 += 16) {
#pragma unroll
        for (int t = 0; t < 4; t++) {
            int o = oA + 8 * t;
            As[kkA][o] = w_out[(o0 + o) * 512 + k0 + kkA];
        }
#pragma unroll
        for (int t = 0; t < 8; t++) {
            int kk = kB + 2 * t;
            Bs[kk][nB] = g_o[((size_t)bb * 512 + k0 + kk) * N_TOK + n0 + nB];
        }
        __syncthreads();
#pragma unroll
        for (int kk = 0; kk < 16; kk++) {
            float a[4], b[4];
#pragma unroll
            for (int x = 0; x < 4; x++) a[x] = As[kk][tr * 4 + x];
#pragma unroll
            for (int y = 0; y < 4; y++) b[y] = Bs[kk][tc * 4 + y];
#pragma unroll
            for (int x = 0; x < 4; x++)
#pragma unroll
                for (int y = 0; y < 4; y++) acc[x][y] = fmaf(a[x], b[y], acc[x][y]);
        }
        __syncthreads();
    }
#pragma unroll
    for (int x = 0; x < 4; x++)
#pragma unroll
        for (int y = 0; y < 4; y++)
            out[(size_t)bb * 256 * N_TOK + (size_t)(o0 + tr * 4 + x) * N_TOK + n0 + tc * 4 + y] = acc[x][y];
}

// ---------------- launch ----------------
extern "C" void kernel_launch(void* const* d_in, const int* in_sizes, int n_in,
                              void* d_out, int out_size) {
    const float* fmap   = (const float*)d_in[0];
    const float* gamma  = (const float*)d_in[1];
    const float* w_qk   = (const float*)d_in[2];
    const float* w_v    = (const float*)d_in[3];
    const float* nullkv = (const float*)d_in[4];
    const float* w_out  = (const float*)d_in[5];
    float* out = (float*)d_out;

    cudaFuncSetAttribute(attn_mma_kernel, cudaFuncAttributeMaxDynamicSharedMemorySize, SM_TOT);

    null_init<<<1, 128>>>(nullkv);
    wscale_kernel<<<(512 * C_IN) / 256, 256>>>(w_qk, w_v, gamma);
    norm_kernel<<<(B_ * N_TOK) / 32, 256>>>(fmap);
    proj_mma_kernel<<<dim3(N_TOK / 128, 16, B_), 256>>>(fmap);
    attn_mma_kernel<<<dim3(N_TOK / 128, H_, B_), 256, SM_TOT>>>();
    outproj_kernel<<<dim3(N_TOK / 64, 8, B_), 128>>>(w_out, out);
}

// round 16
// speedup vs baseline: 1.7826x; 1.3678x over previous
#include <cuda_runtime.h>
#include <cuda_fp16.h>
#include <math.h>
#include <stdint.h>

#define B_    2
#define C_IN  256
#define N_TOK 2304
#define H_    8
#define DH    64
#define NKV   2305    // n + 1 null token
#define NKVP  2368    // padded (37*64)

typedef unsigned int u32;

// -------- scratch (device globals, zero-init) --------
__device__ float  g_invl2[B_ * N_TOK];
__device__ float  g_wq[512 * C_IN];            // w_qk * gamma
__device__ float  g_wv[512 * C_IN];            // w_v  * gamma
__device__ __half g_kb[B_ * H_ * NKV * DH];    // [bh][j][d]; row0=null k, row j=q[j-1]; f16
__device__ __half g_vT[B_ * H_ * DH * NKVP];   // [bh][d][j]; col0=null v; f16; pad zeros
__device__ float  g_k2[B_ * H_ * NKVP];        // |k|^2 of f16-rounded rows; pad zeros
__device__ float  g_o [B_ * H_ * DH * N_TOK];  // attn out [bh][d][i] fp32

// -------- helpers --------
__device__ __forceinline__ void mmaf16(float c[4], const u32 a[4], u32 b0, u32 b1) {
    asm("mma.sync.aligned.m16n8k16.row.col.f32.f16.f16.f32 "
        "{%0,%1,%2,%3},{%4,%5,%6,%7},{%8,%9},{%0,%1,%2,%3};"
        : "+f"(c[0]), "+f"(c[1]), "+f"(c[2]), "+f"(c[3])
        : "r"(a[0]), "r"(a[1]), "r"(a[2]), "r"(a[3]), "r"(b0), "r"(b1));
}
__device__ __forceinline__ void mmat32(float c[4], const u32 a[4], u32 b0, u32 b1) {
    asm("mma.sync.aligned.m16n8k8.row.col.f32.tf32.tf32.f32 "
        "{%0,%1,%2,%3},{%4,%5,%6,%7},{%8,%9},{%0,%1,%2,%3};"
        : "+f"(c[0]), "+f"(c[1]), "+f"(c[2]), "+f"(c[3])
        : "r"(a[0]), "r"(a[1]), "r"(a[2]), "r"(a[3]), "r"(b0), "r"(b1));
}
__device__ __forceinline__ void ldsm4(u32& r0, u32& r1, u32& r2, u32& r3, u32 addr) {
    asm volatile("ldmatrix.sync.aligned.m8n8.x4.shared.b16 {%0,%1,%2,%3}, [%4];"
        : "=r"(r0), "=r"(r1), "=r"(r2), "=r"(r3) : "r"(addr));
}
__device__ __forceinline__ u32 packh2(float hi, float lo) {
    u32 r; asm("cvt.rn.f16x2.f32 %0, %1, %2;" : "=r"(r) : "f"(hi), "f"(lo)); return r;
}
__device__ __forceinline__ void cpasync16(u32 dst, const void* src) {
    asm volatile("cp.async.ca.shared.global [%0], [%1], 16;" :: "r"(dst), "l"(src));
}
__device__ __forceinline__ void cpcommit() { asm volatile("cp.async.commit_group;"); }

// ---------------- 0a) null token rows ----------------
__global__ void null_init(const float* __restrict__ nullkv) {
    int tid = threadIdx.x;  // 128
#pragma unroll
    for (int t = 0; t < 8; t++) {
        int idx = tid + 128 * t;                 // 0..1023
        int bh = idx >> 6, d = idx & 63, h = bh & 7;
        g_kb[(size_t)bh * NKV * DH + d]  = __float2half_rn(nullkv[h * DH + d]);
        g_vT[((size_t)bh * DH + d) * NKVP] = __float2half_rn(nullkv[H_ * DH + h * DH + d]);
    }
    if (tid < 16) {
        int h = tid & 7; float s = 0.f;
#pragma unroll 8
        for (int d = 0; d < 64; d++) {
            float x = __half2float(__float2half_rn(nullkv[h * DH + d]));
            s = fmaf(x, x, s);
        }
        g_k2[(size_t)tid * NKVP] = s;
    }
}

// ---------------- 0b) pre-scale weights by gamma ----------------
__global__ __launch_bounds__(256) void wscale_kernel(const float* __restrict__ w_qk,
                                                     const float* __restrict__ w_v,
                                                     const float* __restrict__ gamma) {
    int idx = blockIdx.x * 256 + threadIdx.x;
    int c = idx & (C_IN - 1);
    float g = gamma[c];
    g_wq[idx] = w_qk[idx] * g;
    g_wv[idx] = w_v[idx] * g;
}

// ---------------- 1) per-token inverse L2 norm ----------------
__global__ __launch_bounds__(256) void norm_kernel(const float* __restrict__ fmap) {
    __shared__ float part[8][33];
    int i_loc = threadIdx.x & 31, cg = threadIdx.x >> 5;
    int idx = blockIdx.x * 32 + i_loc;
    int bb = idx / N_TOK, i = idx - bb * N_TOK;
    const float* p = fmap + (size_t)bb * C_IN * N_TOK + (size_t)cg * 32 * N_TOK + i;
    float s = 0.f;
#pragma unroll 8
    for (int c = 0; c < 32; c++) { float x = p[(size_t)c * N_TOK]; s = fmaf(x, x, s); }
    part[cg][i_loc] = s;
    __syncthreads();
    if (threadIdx.x < 32) {
        float t = 0.f;
#pragma unroll
        for (int g = 0; g < 8; g++) t += part[g][threadIdx.x];
        g_invl2[blockIdx.x * 32 + threadIdx.x] = 16.0f / fmaxf(sqrtf(t), 1e-12f);
    }
}

// ---------------- 2) qk/v projection via tf32 mma ----------------
#define PA_ST 136
#define PB_ST 20
#define P_BUFA (16 * PA_ST)
#define P_BSB  (2 * P_BUFA)
#define P_BUFB (64 * PB_ST)

__global__ __launch_bounds__(256) void proj_mma_kernel(const float* __restrict__ fmap) {
    __shared__ float sm[P_BSB + 2 * P_BUFB];
    u32* smw = (u32*)sm;
    u32 smu = (u32)__cvta_generic_to_shared(sm);

    const int tid = threadIdx.x, lane = tid & 31, w = tid >> 5;
    const int i0 = blockIdx.x * 128;
    const int y  = blockIdx.y;
    const bool isv = (y >= 8);
    const int h = y & 7;
    const int bb = blockIdx.z, bh = bb * H_ + h;
    const float* Wg = (isv ? g_wv : g_wq) + (size_t)h * 64 * C_IN;
    const float* Ab = fmap + (size_t)bb * C_IN * N_TOK + i0;

    const int r0 = lane >> 2, cq = lane & 3;
    const int il0 = w * 16 + r0;
    const int ig0 = i0 + il0, ig1 = ig0 + 8;

    float co[8][4];
#pragma unroll
    for (int n = 0; n < 8; n++) { co[n][0] = co[n][1] = co[n][2] = co[n][3] = 0.f; }

    auto load_tile = [&](int buf, int k0) {
#pragma unroll
        for (int it = 0; it < 3; it++) {
            int c = tid + 256 * it;
            if (c < 512) {
                int cr = c >> 5, ck = c & 31;
                cpasync16(smu + (u32)(buf * P_BUFA + cr * PA_ST + ck * 4) * 4,
                          Ab + (size_t)(k0 + cr) * N_TOK + ck * 4);
            } else {
                int cc = c - 512;
                int o = cc >> 2, ck = cc & 3;
                cpasync16(smu + (u32)(P_BSB + buf * P_BUFB + o * PB_ST + ck * 4) * 4,
                          Wg + (size_t)o * C_IN + k0 + ck * 4);
            }
        }
    };

    load_tile(0, 0);
    cpcommit();

    const int NKT = C_IN / 16;
    for (int t = 0; t < NKT; t++) {
        const int buf = t & 1;
        if (t + 1 < NKT) {
            if (t >= 1) __syncthreads();
            load_tile(buf ^ 1, (t + 1) * 16);
            cpcommit();
            asm volatile("cp.async.wait_group 1;");
        } else {
            asm volatile("cp.async.wait_group 0;");
        }
        __syncthreads();

        const u32* As = smw + buf * P_BUFA;
        const u32* Bs = smw + P_BSB + buf * P_BUFB;
#pragma unroll
        for (int ks = 0; ks < 2; ks++) {
            int cb = ks * 8;
            u32 a[4];
            a[0] = As[(cb + cq) * PA_ST + il0];
            a[1] = As[(cb + cq) * PA_ST + il0 + 8];
            a[2] = As[(cb + cq + 4) * PA_ST + il0];
            a[3] = As[(cb + cq + 4) * PA_ST + il0 + 8];
#pragma unroll
            for (int n = 0; n < 8; n++) {
                u32 b0 = Bs[(n * 8 + r0) * PB_ST + cb + cq];
                u32 b1 = Bs[(n * 8 + r0) * PB_ST + cb + cq + 4];
                mmat32(co[n], a, b0, b1);
            }
        }
    }

    const float sc0 = g_invl2[bb * N_TOK + ig0];
    const float sc1 = g_invl2[bb * N_TOK + ig1];
    if (!isv) {
        float rs0 = 0.f, rs1 = 0.f;
#pragma unroll
        for (int n = 0; n < 8; n++) {
            int d = n * 8 + 2 * cq;
            u32 h0 = packh2(co[n][1] * sc0, co[n][0] * sc0);
            u32 h1 = packh2(co[n][3] * sc1, co[n][2] * sc1);
            *(u32*)&g_kb[((size_t)bh * NKV + ig0 + 1) * DH + d] = h0;
            *(u32*)&g_kb[((size_t)bh * NKV + ig1 + 1) * DH + d] = h1;
            __half2 hh0 = *(__half2*)&h0, hh1 = *(__half2*)&h1;
            float a0 = __low2float(hh0), a1 = __high2float(hh0);
            float b0f = __low2float(hh1), b1f = __high2float(hh1);
            rs0 = fmaf(a0, a0, fmaf(a1, a1, rs0));
            rs1 = fmaf(b0f, b0f, fmaf(b1f, b1f, rs1));
        }
        rs0 += __shfl_xor_sync(~0u, rs0, 1); rs0 += __shfl_xor_sync(~0u, rs0, 2);
        rs1 += __shfl_xor_sync(~0u, rs1, 1); rs1 += __shfl_xor_sync(~0u, rs1, 2);
        if (cq == 0) {
            g_k2[(size_t)bh * NKVP + ig0 + 1] = rs0;
            g_k2[(size_t)bh * NKVP + ig1 + 1] = rs1;
        }
    } else {
        __half* vb = g_vT + (size_t)bh * DH * NKVP;
#pragma unroll
        for (int n = 0; n < 8; n++) {
            int d = n * 8 + 2 * cq;
            vb[(size_t)d * NKVP + ig0 + 1]       = __float2half_rn(co[n][0] * sc0);
            vb[(size_t)(d + 1) * NKVP + ig0 + 1] = __float2half_rn(co[n][1] * sc0);
            vb[(size_t)d * NKVP + ig1 + 1]       = __float2half_rn(co[n][2] * sc1);
            vb[(size_t)(d + 1) * NKVP + ig1 + 1] = __float2half_rn(co[n][3] * sc1);
        }
    }
}

// ---------------- 3) flash attention: ldmatrix + register-resident P ----------------
#define SMK_W  0
#define SMV_W  4096
#define SMK2_W 8192
#define SM_TOT ((SMK2_W + 128) * 4)   // 33280 B

__global__ __launch_bounds__(256, 2) void attn_mma_kernel() {
    extern __shared__ float sm[];
    const int tid = threadIdx.x, lane = tid & 31, w = tid >> 5;   // 8 warps
    const int i0 = blockIdx.x * 128, h = blockIdx.y, bb = blockIdx.z;
    const int bh = bb * H_ + h;
    const __half* kb_g = g_kb + (size_t)bh * NKV * DH;
    const __half* vT_g = g_vT + (size_t)bh * DH * NKVP;
    const float*  k2g  = g_k2 + (size_t)bh * NKVP;
    u32 smu = (u32)__cvta_generic_to_shared(sm);

    const int r0 = lane >> 2, cq = lane & 3;
    const int iw  = i0 + w * 16;
    const int ig0 = iw + r0, ig1 = ig0 + 8;

    // ldmatrix lane constants
    const int lm = lane >> 3, lrow = lane & 7;
    const int jc  = 8 * (lm >> 1) + lrow;
    const int ch0 = lm & 1;

    // Q A-fragments
    u32 aq[4][4];
    {
        const __half* q0 = kb_g + (size_t)(ig0 + 1) * DH;
        const __half* q1 = kb_g + (size_t)(ig1 + 1) * DH;
#pragma unroll
        for (int kk = 0; kk < 4; kk++) {
            int d = kk * 16 + 2 * cq;
            aq[kk][0] = *(const u32*)(q0 + d);
            aq[kk][1] = *(const u32*)(q1 + d);
            aq[kk][2] = *(const u32*)(q0 + d + 8);
            aq[kk][3] = *(const u32*)(q1 + d + 8);
        }
    }
    const float q2r0 = k2g[ig0 + 1], q2r1 = k2g[ig1 + 1];

    float l0 = 0.f, l1 = 0.f;
    float o[8][4];
#pragma unroll
    for (int n = 0; n < 8; n++) { o[n][0] = o[n][1] = o[n][2] = o[n][3] = 0.f; }

    auto load_tile = [&](int buf, int j0) {
#pragma unroll
        for (int it = 0; it < 5; it++) {
            int c = tid + 256 * it;
            if (c < 512) {
                int row = c >> 3, ch = c & 7, sw = ch ^ (row & 7);
                int jg = j0 + row; if (jg > NKV - 1) jg = NKV - 1;
                cpasync16(smu + (u32)(SMK_W + buf * 2048 + row * 32 + sw * 4) * 4,
                          kb_g + (size_t)jg * DH + ch * 8);
            } else if (c < 1024) {
                int cc = c - 512;
                int row = cc >> 3, ch = cc & 7, sw = ch ^ (row & 7);
                cpasync16(smu + (u32)(SMV_W + buf * 2048 + row * 32 + sw * 4) * 4,
                          vT_g + (size_t)row * NKVP + j0 + ch * 8);
            } else if (c < 1040) {
                int cc = c - 1024;
                cpasync16(smu + (u32)(SMK2_W + buf * 64 + cc * 4) * 4, k2g + j0 + cc * 4);
            }
        }
    };

    load_tile(0, 0);
    cpcommit();

    const int NT = (NKV + 63) / 64;   // 37
    for (int t = 0; t < NT; t++) {
        const int j0 = t * 64, buf = t & 1;
        if (t + 1 < NT) {
            if (t >= 1) __syncthreads();
            load_tile(buf ^ 1, j0 + 64);
            cpcommit();
            asm volatile("cp.async.wait_group 1;");
        } else {
            asm volatile("cp.async.wait_group 0;");
        }
        __syncthreads();

        const u32 kbase = smu + (u32)(SMK_W + buf * 2048) * 4 + (u32)jc * 128;
        const u32 vbase = smu + (u32)(SMV_W + buf * 2048) * 4 + (u32)jc * 128;
        const float* k2s = sm + SMK2_W + buf * 64;

        // ---- S = Q K^T : ldmatrix.x4 B-frags ----
        float sC[8][4];
#pragma unroll
        for (int n = 0; n < 8; n++) { sC[n][0] = sC[n][1] = sC[n][2] = sC[n][3] = 0.f; }
#pragma unroll
        for (int kk = 0; kk < 4; kk++) {
            const u32 chx = (u32)(((2 * kk + ch0) ^ lrow) * 16);
#pragma unroll
            for (int np = 0; np < 4; np++) {
                u32 b0, b1, b2, b3;
                ldsm4(b0, b1, b2, b3, kbase + (u32)np * 2048 + chx);
                mmaf16(sC[2 * np],     aq[kk], b0, b1);
                mmaf16(sC[2 * np + 1], aq[kk], b2, b3);
            }
        }

        // ---- p = exp(-sqrt(d2)/8) (m=0), masks, l; pack to PV A-frags ----
        u32 pp[8][2];
#pragma unroll
        for (int n = 0; n < 8; n++) {
            int jbase = j0 + n * 8;
            float2 kk2 = *(const float2*)(k2s + n * 8 + 2 * cq);
            float p0 = __expf(-0.125f * sqrtf(fmaxf(fmaf(-2.f, sC[n][0], q2r0 + kk2.x), 0.f)));
            float p1 = __expf(-0.125f * sqrtf(fmaxf(fmaf(-2.f, sC[n][1], q2r0 + kk2.y), 0.f)));
            float p2 = __expf(-0.125f * sqrtf(fmaxf(fmaf(-2.f, sC[n][2], q2r1 + kk2.x), 0.f)));
            float p3 = __expf(-0.125f * sqrtf(fmaxf(fmaf(-2.f, sC[n][3], q2r1 + kk2.y), 0.f)));
            if ((jbase <= iw + 16 && jbase + 8 > iw + 1) || (jbase + 8 > NKV)) {
                int jb = jbase + 2 * cq;
                if (jb == ig0 + 1 || jb >= NKV)         p0 = 0.f;
                if (jb + 1 == ig0 + 1 || jb + 1 >= NKV) p1 = 0.f;
                if (jb == ig1 + 1 || jb >= NKV)         p2 = 0.f;
                if (jb + 1 == ig1 + 1 || jb + 1 >= NKV) p3 = 0.f;
            }
            l0 += p0 + p1; l1 += p2 + p3;
            pp[n][0] = packh2(p1, p0);
            pp[n][1] = packh2(p3, p2);
        }

        // ---- O += P V : register A-frags, ldmatrix.x4 V B-frags ----
#pragma unroll
        for (int kk = 0; kk < 4; kk++) {
            u32 ap[4];
            ap[0] = pp[2 * kk][0];
            ap[1] = pp[2 * kk][1];
            ap[2] = pp[2 * kk + 1][0];
            ap[3] = pp[2 * kk + 1][1];
            const u32 chx = (u32)(((2 * kk + ch0) ^ lrow) * 16);
#pragma unroll
            for (int np = 0; np < 4; np++) {
                u32 b0, b1, b2, b3;
                ldsm4(b0, b1, b2, b3, vbase + (u32)np * 2048 + chx);
                mmaf16(o[2 * np],     ap, b0, b1);
                mmaf16(o[2 * np + 1], ap, b2, b3);
            }
        }
    }

    // ---- epilogue ----
    l0 += __shfl_xor_sync(~0u, l0, 1); l0 += __shfl_xor_sync(~0u, l0, 2);
    l1 += __shfl_xor_sync(~0u, l1, 1); l1 += __shfl_xor_sync(~0u, l1, 2);
    float inv0 = 1.f / l0, inv1 = 1.f / l1;
    float* ob = g_o + (size_t)bh * DH * N_TOK;
#pragma unroll
    for (int n = 0; n < 8; n++) {
        int d = n * 8 + 2 * cq;
        ob[(size_t)d * N_TOK + ig0]       = o[n][0] * inv0;
        ob[(size_t)(d + 1) * N_TOK + ig0] = o[n][1] * inv0;
        ob[(size_t)d * N_TOK + ig1]       = o[n][2] * inv1;
        ob[(size_t)(d + 1) * N_TOK + ig1] = o[n][3] * inv1;
    }
}

// ---------------- 4) output projection GEMM ----------------
__global__ __launch_bounds__(128) void outproj_kernel(const float* __restrict__ w_out,
                                                      float* __restrict__ out) {
    __shared__ float As[16][32];
    __shared__ float Bs[16][64];
    const int n0 = blockIdx.x * 64, o0 = blockIdx.y * 32, bb = blockIdx.z;
    const int tid = threadIdx.x, tr = tid >> 4, tc = tid & 15;
    const int kkA = tid & 15, oA = tid >> 4;
    const int nB = tid & 63, kB = tid >> 6;
    float acc[4][4] = {};
    for (int k0 = 0; k0 < 512; k0 += 16) {
#pragma unroll
        for (int t = 0; t < 4; t++) {
            int o = oA + 8 * t;
            As[kkA][o] = w_out[(o0 + o) * 512 + k0 + kkA];
        }
#pragma unroll
        for (int t = 0; t < 8; t++) {
            int kk = kB + 2 * t;
            Bs[kk][nB] = g_o[((size_t)bb * 512 + k0 + kk) * N_TOK + n0 + nB];
        }
        __syncthreads();
#pragma unroll
        for (int kk = 0; kk < 16; kk++) {
            float a[4], b[4];
#pragma unroll
            for (int x = 0; x < 4; x++) a[x] = As[kk][tr * 4 + x];
#pragma unroll
            for (int y = 0; y < 4; y++) b[y] = Bs[kk][tc * 4 + y];
#pragma unroll
            for (int x = 0; x < 4; x++)
#pragma unroll
                for (int y = 0; y < 4; y++) acc[x][y] = fmaf(a[x], b[y], acc[x][y]);
        }
        __syncthreads();
    }
#pragma unroll
    for (int x = 0; x < 4; x++)
#pragma unroll
        for (int y = 0; y < 4; y++)
            out[(size_t)bb * 256 * N_TOK + (size_t)(o0 + tr * 4 + x) * N_TOK + n0 + tc * 4 + y] = acc[x][y];
}

// ---------------- launch ----------------
extern "C" void kernel_launch(void* const* d_in, const int* in_sizes, int n_in,
                              void* d_out, int out_size) {
    const float* fmap   = (const float*)d_in[0];
    const float* gamma  = (const float*)d_in[1];
    const float* w_qk   = (const float*)d_in[2];
    const float* w_v    = (const float*)d_in[3];
    const float* nullkv = (const float*)d_in[4];
    const float* w_out  = (const float*)d_in[5];
    float* out = (float*)d_out;

    cudaFuncSetAttribute(attn_mma_kernel, cudaFuncAttributeMaxDynamicSharedMemorySize, SM_TOT);

    null_init<<<1, 128>>>(nullkv);
    wscale_kernel<<<(512 * C_IN) / 256, 256>>>(w_qk, w_v, gamma);
    norm_kernel<<<(B_ * N_TOK) / 32, 256>>>(fmap);
    proj_mma_kernel<<<dim3(N_TOK / 128, 16, B_), 256>>>(fmap);
    attn_mma_kernel<<<dim3(N_TOK / 128, H_, B_), 256, SM_TOT>>>();
    outproj_kernel<<<dim3(N_TOK / 64, 8, B_), 128>>>(w_out, out);
}